// round 2
// baseline (speedup 1.0000x reference)
#include <cuda_runtime.h>
#include <math.h>

// Problem constants
#define BVN   32          // B*V
#define SEQ   512
#define EMB   1024
#define NH    16
#define HD    64
#define NQKV  3072        // 3*EMB
#define MROWS (BVN*SEQ)   // 16384
#define QKV_SZ (BVN*NH*SEQ*HD)  // 16,777,216 floats per Q/K/V

// Scratch (allocation-free: __device__ globals)
__device__ float g_qkv[3u * QKV_SZ];   // [qkv][bv][h][s][d]
__device__ float g_att[QKV_SZ];        // [bv][s][h][d]

// ---------------------------------------------------------------------------
// Tiled SIMT fp32 GEMM: C[M,N] = A[M,K] @ B[K,N] + bias
// BM=BN=128, BK=16, 256 threads, 8x8 per thread, ping-pong smem.
// MODE 0: plain row-major C (used for output projection -> d_out)
// MODE 1: scatter epilogue into Q/K/V scratch with layout [qkv][bv][h][s][d];
//         thread columns are strided by 16 so each thread's 8 outputs are
//         contiguous d for a fixed head -> two float4 stores.
// ---------------------------------------------------------------------------
template<int MODE>
__global__ __launch_bounds__(256, 2)
void gemm128(const float* __restrict__ A, const float* __restrict__ B,
             const float* __restrict__ bias, float* __restrict__ C,
             int M, int N, int K)
{
    __shared__ float As[2][16][128];
    __shared__ float Bs[2][16][128];

    const int tid = threadIdx.x;
    const int tx = tid & 15, ty = tid >> 4;
    const int n0 = blockIdx.x * 128;
    const int m0 = blockIdx.y * 128;

    // A-tile load mapping: 128 rows x 16 cols = 512 float4, 2 per thread
    const int arow0 = tid >> 2;              // 0..63
    const int arow1 = arow0 + 64;
    const int ac    = (tid & 3) * 4;         // 0,4,8,12
    // B-tile load mapping: 16 rows x 128 cols = 512 float4, 2 per thread
    const int brow0 = tid >> 5;              // 0..7
    const int brow1 = brow0 + 8;
    const int bc    = (tid & 31) * 4;        // 0..124

    const float* Ap0 = A + (size_t)(m0 + arow0) * K + ac;
    const float* Ap1 = A + (size_t)(m0 + arow1) * K + ac;
    const float* Bp0 = B + (size_t)brow0 * N + n0 + bc;
    const float* Bp1 = B + (size_t)brow1 * N + n0 + bc;

    float acc[8][8];
    #pragma unroll
    for (int i = 0; i < 8; i++)
        #pragma unroll
        for (int j = 0; j < 8; j++) acc[i][j] = 0.f;

    // Prologue: tile 0 -> buffer 0
    {
        float4 ra0 = *(const float4*)Ap0;
        float4 ra1 = *(const float4*)Ap1;
        float4 rb0 = *(const float4*)Bp0;
        float4 rb1 = *(const float4*)Bp1;
        As[0][ac+0][arow0] = ra0.x; As[0][ac+1][arow0] = ra0.y;
        As[0][ac+2][arow0] = ra0.z; As[0][ac+3][arow0] = ra0.w;
        As[0][ac+0][arow1] = ra1.x; As[0][ac+1][arow1] = ra1.y;
        As[0][ac+2][arow1] = ra1.z; As[0][ac+3][arow1] = ra1.w;
        *(float4*)&Bs[0][brow0][bc] = rb0;
        *(float4*)&Bs[0][brow1][bc] = rb1;
    }
    __syncthreads();

    const int nk = K >> 4;
    for (int kt = 0; kt < nk; kt++) {
        const int cur = kt & 1;
        float4 ra0, ra1, rb0, rb1;
        const bool pf = (kt + 1 < nk);
        if (pf) {
            const int ko = (kt + 1) << 4;
            ra0 = *(const float4*)(Ap0 + ko);
            ra1 = *(const float4*)(Ap1 + ko);
            rb0 = *(const float4*)(Bp0 + (size_t)ko * N);
            rb1 = *(const float4*)(Bp1 + (size_t)ko * N);
        }
        #pragma unroll
        for (int kk = 0; kk < 16; kk++) {
            float av[8], bw[8];
            float4 a0 = *(const float4*)&As[cur][kk][ty * 8];
            float4 a1 = *(const float4*)&As[cur][kk][ty * 8 + 4];
            av[0]=a0.x; av[1]=a0.y; av[2]=a0.z; av[3]=a0.w;
            av[4]=a1.x; av[5]=a1.y; av[6]=a1.z; av[7]=a1.w;
            if (MODE == 1) {
                #pragma unroll
                for (int j = 0; j < 8; j++) bw[j] = Bs[cur][kk][tx + 16 * j];
            } else {
                float4 b0 = *(const float4*)&Bs[cur][kk][tx * 8];
                float4 b1 = *(const float4*)&Bs[cur][kk][tx * 8 + 4];
                bw[0]=b0.x; bw[1]=b0.y; bw[2]=b0.z; bw[3]=b0.w;
                bw[4]=b1.x; bw[5]=b1.y; bw[6]=b1.z; bw[7]=b1.w;
            }
            #pragma unroll
            for (int i = 0; i < 8; i++)
                #pragma unroll
                for (int j = 0; j < 8; j++) acc[i][j] += av[i] * bw[j];
        }
        if (pf) {
            const int nxt = cur ^ 1;
            As[nxt][ac+0][arow0] = ra0.x; As[nxt][ac+1][arow0] = ra0.y;
            As[nxt][ac+2][arow0] = ra0.z; As[nxt][ac+3][arow0] = ra0.w;
            As[nxt][ac+0][arow1] = ra1.x; As[nxt][ac+1][arow1] = ra1.y;
            As[nxt][ac+2][arow1] = ra1.z; As[nxt][ac+3][arow1] = ra1.w;
            *(float4*)&Bs[nxt][brow0][bc] = rb0;
            *(float4*)&Bs[nxt][brow1][bc] = rb1;
        }
        __syncthreads();
    }

    if (MODE == 0) {
        float bb[8];
        #pragma unroll
        for (int j = 0; j < 8; j++) bb[j] = bias[n0 + tx * 8 + j];
        #pragma unroll
        for (int i = 0; i < 8; i++) {
            const int row = m0 + ty * 8 + i;
            float4* dst = (float4*)(C + (size_t)row * N + n0 + tx * 8);
            dst[0] = make_float4(acc[i][0]+bb[0], acc[i][1]+bb[1],
                                 acc[i][2]+bb[2], acc[i][3]+bb[3]);
            dst[1] = make_float4(acc[i][4]+bb[4], acc[i][5]+bb[5],
                                 acc[i][6]+bb[6], acc[i][7]+bb[7]);
        }
    } else {
        // Column c = n0 + tx + 16*j.  Reference split order is (3, D, H):
        //   c = qkvi*1024 + d*16 + h  ->  h = tx (n0 % 16 == 0), d = (n0%1024)/16 + j
        float bb[8];
        #pragma unroll
        for (int j = 0; j < 8; j++) bb[j] = bias[n0 + tx + 16 * j];
        const int qkvi = n0 / 1024;
        const int di0  = (n0 & 1023) >> 4;   // multiple of 8
        const int h    = tx;
        float* base = C + (size_t)qkvi * QKV_SZ;
        #pragma unroll
        for (int i = 0; i < 8; i++) {
            const int row = m0 + ty * 8 + i;
            const int bv = row >> 9, s = row & 511;
            float* dst = base + (((size_t)(bv * NH + h) * SEQ + s) * HD + di0);
            *(float4*)(dst)     = make_float4(acc[i][0]+bb[0], acc[i][1]+bb[1],
                                              acc[i][2]+bb[2], acc[i][3]+bb[3]);
            *(float4*)(dst + 4) = make_float4(acc[i][4]+bb[4], acc[i][5]+bb[5],
                                              acc[i][6]+bb[6], acc[i][7]+bb[7]);
        }
    }
}

// ---------------------------------------------------------------------------
// Flash attention: one block = (bv, h, 128-query tile), 128 threads,
// one query row per thread (q[64], acc[64] in regs).  K/V tiles of 64 keys in
// smem; per-tile scores staged in padded smem (pitch 65 -> conflict-free) so
// the t-loops stay dynamic and register count stays ~160.
// ---------------------------------------------------------------------------
#define ATTN_SMEM ((64*64 + 64*64 + 128*65) * 4)   // 66048 bytes

__global__ __launch_bounds__(128)
void attn_kernel(const float* __restrict__ QKV, float* __restrict__ O)
{
    extern __shared__ float sm[];
    float* Ks = sm;            // 64 x 64
    float* Vs = sm + 4096;     // 64 x 64
    float* Ss = sm + 8192;     // 128 x 65 (padded)

    const int tid = threadIdx.x;
    const int qt = blockIdx.x, h = blockIdx.y, bv = blockIdx.z;
    const int srow = qt * 128 + tid;

    const float* Qb = QKV + (((size_t)(bv * NH + h)) * SEQ + srow) * HD;
    const float* Kb = QKV + (size_t)QKV_SZ     + ((size_t)(bv * NH + h)) * SEQ * HD;
    const float* Vb = QKV + (size_t)2 * QKV_SZ + ((size_t)(bv * NH + h)) * SEQ * HD;

    float q[64];
    {
        const float4* qp = (const float4*)Qb;
        #pragma unroll
        for (int i = 0; i < 16; i++) {
            float4 v = qp[i];
            q[4*i] = v.x; q[4*i+1] = v.y; q[4*i+2] = v.z; q[4*i+3] = v.w;
        }
    }

    float acc[64];
    #pragma unroll
    for (int d = 0; d < 64; d++) acc[d] = 0.f;
    float mx = -1e30f, l = 0.f;
    float* myrow = Ss + tid * 65;

    for (int kt = 0; kt < 8; kt++) {
        __syncthreads();
        const float4* ksrc = (const float4*)(Kb + (size_t)kt * 64 * 64);
        const float4* vsrc = (const float4*)(Vb + (size_t)kt * 64 * 64);
        #pragma unroll
        for (int i = 0; i < 8; i++) {
            ((float4*)Ks)[tid + i * 128] = ksrc[tid + i * 128];
            ((float4*)Vs)[tid + i * 128] = vsrc[tid + i * 128];
        }
        __syncthreads();

        float tm = -1e30f;
        #pragma unroll 2
        for (int t = 0; t < 64; t++) {
            const float* kr = Ks + t * 64;
            float s0 = 0.f, s1 = 0.f, s2 = 0.f, s3 = 0.f;
            #pragma unroll
            for (int d = 0; d < 64; d += 4) {
                s0 += q[d]   * kr[d];
                s1 += q[d+1] * kr[d+1];
                s2 += q[d+2] * kr[d+2];
                s3 += q[d+3] * kr[d+3];
            }
            float sv = ((s0 + s1) + (s2 + s3)) * 0.125f;  // 1/sqrt(64)
            myrow[t] = sv;
            tm = fmaxf(tm, sv);
        }

        const float newm = fmaxf(mx, tm);
        const float corr = __expf(mx - newm);
        l *= corr;
        #pragma unroll
        for (int d = 0; d < 64; d++) acc[d] *= corr;

        #pragma unroll 2
        for (int t = 0; t < 64; t++) {
            const float p = __expf(myrow[t] - newm);
            l += p;
            const float* vr = Vs + t * 64;
            #pragma unroll
            for (int d = 0; d < 64; d++) acc[d] += p * vr[d];
        }
        mx = newm;
    }

    const float inv = 1.f / l;
    float4* op = (float4*)(O + (((size_t)(bv * SEQ + srow)) * NH + h) * HD);
    #pragma unroll
    for (int i = 0; i < 16; i++)
        op[i] = make_float4(acc[4*i] * inv, acc[4*i+1] * inv,
                            acc[4*i+2] * inv, acc[4*i+3] * inv);
}

// ---------------------------------------------------------------------------
extern "C" void kernel_launch(void* const* d_in, const int* in_sizes, int n_in,
                              void* d_out, int out_size)
{
    const float* x    = (const float*)d_in[0];
    const float* Wqkv = (const float*)d_in[1];
    const float* bqkv = (const float*)d_in[2];
    const float* Wo   = (const float*)d_in[3];
    const float* bo   = (const float*)d_in[4];
    float* out = (float*)d_out;

    float *qkv, *att;
    cudaGetSymbolAddress((void**)&qkv, g_qkv);
    cudaGetSymbolAddress((void**)&att, g_att);

    cudaFuncSetAttribute(attn_kernel,
                         cudaFuncAttributeMaxDynamicSharedMemorySize, ATTN_SMEM);

    // 1) QKV projection with transpose epilogue into [qkv][bv][h][s][d]
    gemm128<1><<<dim3(NQKV / 128, MROWS / 128), 256>>>(
        x, Wqkv, bqkv, qkv, MROWS, NQKV, EMB);

    // 2) Flash attention -> [bv][s][h][d]
    attn_kernel<<<dim3(SEQ / 128, NH, BVN), 128, ATTN_SMEM>>>(qkv, att);

    // 3) Output projection -> d_out
    gemm128<0><<<dim3(EMB / 128, MROWS / 128), 256>>>(
        att, Wo, bo, out, MROWS, EMB, EMB);
}

// round 5
// speedup vs baseline: 1.7849x; 1.7849x over previous
#include <cuda_runtime.h>
#include <cuda_bf16.h>
#include <stdint.h>
#include <math.h>

// ---------------------------------------------------------------------------
// Problem constants
// ---------------------------------------------------------------------------
#define BVN   32          // B*V
#define SEQ   512
#define EMB   1024
#define NH    16
#define HD    64
#define NQKV  3072        // 3*EMB
#define MROWS (BVN*SEQ)   // 16384
#define QKV_SZ ((size_t)BVN*NH*SEQ*HD)  // 16,777,216 floats per Q/K/V

// ---------------------------------------------------------------------------
// Scratch (allocation-free: __device__ globals)
// ---------------------------------------------------------------------------
__device__ float         g_qkv[3*QKV_SZ];                 // [qkv][bv][h][s][d] fp32
__device__ __nv_bfloat16 g_Ahi[(size_t)MROWS*EMB];        // x split-hi
__device__ __nv_bfloat16 g_Alo[(size_t)MROWS*EMB];        // x split-lo
__device__ __nv_bfloat16 g_B1hi[(size_t)NQKV*EMB];        // Wqkv^T split-hi  [N,K]
__device__ __nv_bfloat16 g_B1lo[(size_t)NQKV*EMB];
__device__ __nv_bfloat16 g_B2hi[(size_t)EMB*EMB];         // Wo^T split-hi    [N,K]
__device__ __nv_bfloat16 g_B2lo[(size_t)EMB*EMB];
__device__ __nv_bfloat16 g_A2hi[(size_t)MROWS*EMB];       // attention out split-hi
__device__ __nv_bfloat16 g_A2lo[(size_t)MROWS*EMB];

// ---------------------------------------------------------------------------
// Helpers (arch-portable: ldmatrix / mma.sync / cp.async, sm_80+)
// ---------------------------------------------------------------------------
__device__ __forceinline__ uint32_t smem_u32(const void* p) {
    uint32_t a;
    asm("{ .reg .u64 t; cvta.to.shared.u64 t, %1; cvt.u32.u64 %0, t; }" : "=r"(a) : "l"(p));
    return a;
}
#define SW128B(o) ((o) ^ ((((uint32_t)(o)) >> 3) & 0x70u))

__device__ __forceinline__ void cp16(uint32_t s, const void* g) {
    asm volatile("cp.async.cg.shared.global [%0], [%1], 16;" :: "r"(s), "l"(g));
}
__device__ __forceinline__ void cp_commit() {
    asm volatile("cp.async.commit_group;" ::: "memory");
}
template<int N>
__device__ __forceinline__ void cp_wait() {
    asm volatile("cp.async.wait_group %0;" :: "n"(N) : "memory");
}
__device__ __forceinline__ void ldm_x4(uint32_t& r0, uint32_t& r1, uint32_t& r2, uint32_t& r3,
                                       uint32_t addr) {
    asm volatile("ldmatrix.sync.aligned.m8n8.x4.shared.b16 {%0,%1,%2,%3}, [%4];"
                 : "=r"(r0), "=r"(r1), "=r"(r2), "=r"(r3) : "r"(addr));
}
__device__ __forceinline__ void mma16816(float* c, const uint32_t* a, const uint32_t* b) {
    asm volatile("mma.sync.aligned.m16n8k16.row.col.f32.bf16.bf16.f32 "
                 "{%0,%1,%2,%3}, {%4,%5,%6,%7}, {%8,%9}, {%0,%1,%2,%3};"
                 : "+f"(c[0]), "+f"(c[1]), "+f"(c[2]), "+f"(c[3])
                 : "r"(a[0]), "r"(a[1]), "r"(a[2]), "r"(a[3]), "r"(b[0]), "r"(b[1]));
}

// ---------------------------------------------------------------------------
// Pre-pass: fp32 -> bf16 (hi, lo) elementwise, vectorized by 4
// ---------------------------------------------------------------------------
__global__ void cvt_hilo(const float* __restrict__ x,
                         __nv_bfloat16* __restrict__ hi,
                         __nv_bfloat16* __restrict__ lo, int n4)
{
    int i = blockIdx.x * blockDim.x + threadIdx.x;
    if (i >= n4) return;
    float4 v = ((const float4*)x)[i];
    __nv_bfloat16 h0 = __float2bfloat16(v.x), h1 = __float2bfloat16(v.y);
    __nv_bfloat16 h2 = __float2bfloat16(v.z), h3 = __float2bfloat16(v.w);
    __nv_bfloat162 a, b;
    a.x = h0; a.y = h1; b.x = h2; b.y = h3;
    ((__nv_bfloat162*)hi)[2*i] = a; ((__nv_bfloat162*)hi)[2*i+1] = b;
    a.x = __float2bfloat16(v.x - __bfloat162float(h0));
    a.y = __float2bfloat16(v.y - __bfloat162float(h1));
    b.x = __float2bfloat16(v.z - __bfloat162float(h2));
    b.y = __float2bfloat16(v.w - __bfloat162float(h3));
    ((__nv_bfloat162*)lo)[2*i] = a; ((__nv_bfloat162*)lo)[2*i+1] = b;
}

// ---------------------------------------------------------------------------
// Pre-pass: W[K][N] fp32 -> Bt[N][K] bf16 hi/lo (transpose + split)
// ---------------------------------------------------------------------------
__global__ void cvt_transpose(const float* __restrict__ W,
                              __nv_bfloat16* __restrict__ hi,
                              __nv_bfloat16* __restrict__ lo, int K, int N)
{
    __shared__ float t[32][33];
    int nx = blockIdx.x * 32 + threadIdx.x;
    int k0 = blockIdx.y * 32;
    #pragma unroll
    for (int i = 0; i < 4; i++)
        t[threadIdx.y + i*8][threadIdx.x] = W[(size_t)(k0 + threadIdx.y + i*8) * N + nx];
    __syncthreads();
    int kk = k0 + threadIdx.x;
    #pragma unroll
    for (int i = 0; i < 4; i++) {
        int nn = blockIdx.x * 32 + threadIdx.y + i*8;
        float v = t[threadIdx.x][threadIdx.y + i*8];
        __nv_bfloat16 h = __float2bfloat16(v);
        hi[(size_t)nn * K + kk] = h;
        lo[(size_t)nn * K + kk] = __float2bfloat16(v - __bfloat162float(h));
    }
}

// ---------------------------------------------------------------------------
// mma.sync GEMM: C[M,N] = A[M,K] @ Bt[N,K]^T + bias, split-bf16 x3 passes.
// BM=128, BN=128, BK=64, 256 threads (8 warps, 2m x 4n, 64x32 warp tiles),
// SW128-swizzled smem, 2-stage cp.async pipeline.
// MODE 0: row-major fp32 C + bias (output projection -> d_out)
// MODE 1: restage via smem, scatter into g_qkv [qkv][bv][h][s][d]
//         (column c = qkv*1024 + d*16 + h)
// ---------------------------------------------------------------------------
#define STG    65536                     // Ahi16K | Alo16K | Bhi16K | Blo16K
#define MM_SMEM (2*STG)                  // 131072

template<int MODE>
__global__ __launch_bounds__(256)
void gemm_mma(const __nv_bfloat16* __restrict__ Ahi, const __nv_bfloat16* __restrict__ Alo,
              const __nv_bfloat16* __restrict__ Bhi, const __nv_bfloat16* __restrict__ Blo,
              const float* __restrict__ bias, float* __restrict__ C,
              int Ntot, int K)
{
    extern __shared__ char smc[];
    const uint32_t sb = smem_u32(smc);
    const int tid = threadIdx.x, wid = tid >> 5, lane = tid & 31;
    const int wm = wid & 1, wn = wid >> 1;          // 2 x 4 warp grid
    const int n0 = blockIdx.x * 128, m0 = blockIdx.y * 128;
    const int NK = K >> 6;

    // per-thread cp.async source/dest precompute (4 chunks of 16B per array)
    const int crow = tid >> 3;          // 0..31  (+32*i)
    const int cq   = tid & 7;           // 16B chunk in 128B row

    float acc[4][4][4];
    #pragma unroll
    for (int a = 0; a < 4; a++)
        #pragma unroll
        for (int b = 0; b < 4; b++) {
            acc[a][b][0] = 0.f; acc[a][b][1] = 0.f;
            acc[a][b][2] = 0.f; acc[a][b][3] = 0.f;
        }

    // ---- pipeline issue helper (stage s <- k-chunk kc) ----
    auto issue = [&](int s, int kc) {
        const int kb = kc * 64;
        const uint32_t stb = sb + s * STG;
        #pragma unroll
        for (int i = 0; i < 4; i++) {
            const int row = crow + i * 32;
            const uint32_t soff = SW128B(row * 128 + cq * 16);
            const size_t ga = (size_t)(m0 + row) * K + kb + cq * 8;
            const size_t gb = (size_t)(n0 + row) * K + kb + cq * 8;
            cp16(stb + soff,         Ahi + ga);
            cp16(stb + 16384 + soff, Alo + ga);
            cp16(stb + 32768 + soff, Bhi + gb);
            cp16(stb + 49152 + soff, Blo + gb);
        }
        cp_commit();
    };

    issue(0, 0);
    if (NK > 1) issue(1, 1); else cp_commit();

    for (int kc = 0; kc < NK; kc++) {
        const int s = kc & 1;
        if (kc == NK - 1) cp_wait<0>(); else cp_wait<1>();
        __syncthreads();

        const uint32_t sA = sb + s * STG;
        const uint32_t sB = sA + 32768;
        // 3 passes: (Ahi,Bhi), (Ahi,Blo), (Alo,Bhi)
        #pragma unroll
        for (int pass = 0; pass < 3; pass++) {
            const uint32_t pA = sA + ((pass == 2) ? 16384 : 0);
            const uint32_t pB = sB + ((pass == 1) ? 16384 : 0);
            #pragma unroll
            for (int kk = 0; kk < 4; kk++) {
                const int kb = kk * 16;
                uint32_t af[4][4], bf[4][2];
                #pragma unroll
                for (int mi = 0; mi < 4; mi++) {
                    const int r = wm * 64 + mi * 16 + (lane & 15);
                    const int c = kb + (lane >> 4) * 8;
                    ldm_x4(af[mi][0], af[mi][1], af[mi][2], af[mi][3],
                           pA + SW128B(r * 128 + c * 2));
                }
                #pragma unroll
                for (int np = 0; np < 2; np++) {
                    const int r = wn * 32 + np * 16 + ((lane >> 4) & 1) * 8 + (lane & 7);
                    const int c = kb + ((lane >> 3) & 1) * 8;
                    uint32_t q0, q1, q2, q3;
                    ldm_x4(q0, q1, q2, q3, pB + SW128B(r * 128 + c * 2));
                    bf[2*np][0] = q0; bf[2*np][1] = q1;
                    bf[2*np+1][0] = q2; bf[2*np+1][1] = q3;
                }
                #pragma unroll
                for (int mi = 0; mi < 4; mi++)
                    #pragma unroll
                    for (int nj = 0; nj < 4; nj++)
                        mma16816(acc[mi][nj], af[mi], bf[nj]);
            }
        }
        __syncthreads();
        if (kc + 2 < NK) issue(s, kc + 2);
    }

    // ---- epilogue ----
    if (MODE == 0) {
        #pragma unroll
        for (int nj = 0; nj < 4; nj++) {
            const int n = n0 + wn * 32 + nj * 8 + (lane & 3) * 2;
            const float2 bb = *(const float2*)&bias[n];
            #pragma unroll
            for (int mi = 0; mi < 4; mi++) {
                const int m = m0 + wm * 64 + mi * 16 + (lane >> 2);
                float2 v0 = make_float2(acc[mi][nj][0] + bb.x, acc[mi][nj][1] + bb.y);
                float2 v1 = make_float2(acc[mi][nj][2] + bb.x, acc[mi][nj][3] + bb.y);
                *(float2*)(C + (size_t)m * Ntot + n)       = v0;
                *(float2*)(C + (size_t)(m + 8) * Ntot + n) = v1;
            }
        }
    } else {
        // restage through smem (pitch 129 floats -> conflict-free)
        float* Ct = (float*)smc;
        #pragma unroll
        for (int mi = 0; mi < 4; mi++) {
            const int r = wm * 64 + mi * 16 + (lane >> 2);
            #pragma unroll
            for (int nj = 0; nj < 4; nj++) {
                const int c = wn * 32 + nj * 8 + (lane & 3) * 2;
                Ct[r * 129 + c]           = acc[mi][nj][0];
                Ct[r * 129 + c + 1]       = acc[mi][nj][1];
                Ct[(r + 8) * 129 + c]     = acc[mi][nj][2];
                Ct[(r + 8) * 129 + c + 1] = acc[mi][nj][3];
            }
        }
        __syncthreads();
        // column c = n0 + h + 16*j  (h 0..15, j 0..7); qkvi/dbase from n0
        const int qkvi  = n0 >> 10;
        const int dbase = (n0 >> 4) & 63;
        float* outb = C + (size_t)qkvi * QKV_SZ;
        #pragma unroll
        for (int i = 0; i < 8; i++) {
            const int task = tid + i * 256;    // 2048 tasks: (h, mrow)
            const int h    = task >> 7;
            const int mrow = task & 127;
            const int m    = m0 + mrow;
            const int bv = m >> 9, srow = m & 511;
            float v[8];
            #pragma unroll
            for (int j = 0; j < 8; j++)
                v[j] = Ct[mrow * 129 + h + 16 * j] + bias[n0 + h + 16 * j];
            float* dst = outb + (((size_t)(bv * NH + h) * SEQ + srow) * HD + dbase);
            *(float4*)(dst)     = make_float4(v[0], v[1], v[2], v[3]);
            *(float4*)(dst + 4) = make_float4(v[4], v[5], v[6], v[7]);
        }
    }
}

// ---------------------------------------------------------------------------
// Flash attention (unchanged math); epilogue writes split-bf16 for GEMM2.
// ---------------------------------------------------------------------------
#define ATTN_SMEM ((64*64 + 64*64 + 128*65) * 4)   // 66048 bytes

__global__ __launch_bounds__(128)
void attn_kernel(const float* __restrict__ QKV,
                 __nv_bfloat16* __restrict__ Ohi,
                 __nv_bfloat16* __restrict__ Olo)
{
    extern __shared__ float sm[];
    float* Ks = sm;            // 64 x 64
    float* Vs = sm + 4096;     // 64 x 64
    float* Ss = sm + 8192;     // 128 x 65 (padded)

    const int tid = threadIdx.x;
    const int qt = blockIdx.x, h = blockIdx.y, bv = blockIdx.z;
    const int srow = qt * 128 + tid;

    const float* Qb = QKV + (((size_t)(bv * NH + h)) * SEQ + srow) * HD;
    const float* Kb = QKV + QKV_SZ     + ((size_t)(bv * NH + h)) * SEQ * HD;
    const float* Vb = QKV + 2 * QKV_SZ + ((size_t)(bv * NH + h)) * SEQ * HD;

    float q[64];
    {
        const float4* qp = (const float4*)Qb;
        #pragma unroll
        for (int i = 0; i < 16; i++) {
            float4 v = qp[i];
            q[4*i] = v.x; q[4*i+1] = v.y; q[4*i+2] = v.z; q[4*i+3] = v.w;
        }
    }

    float acc[64];
    #pragma unroll
    for (int d = 0; d < 64; d++) acc[d] = 0.f;
    float mx = -1e30f, l = 0.f;
    float* myrow = Ss + tid * 65;

    for (int kt = 0; kt < 8; kt++) {
        __syncthreads();
        const float4* ksrc = (const float4*)(Kb + (size_t)kt * 64 * 64);
        const float4* vsrc = (const float4*)(Vb + (size_t)kt * 64 * 64);
        #pragma unroll
        for (int i = 0; i < 8; i++) {
            ((float4*)Ks)[tid + i * 128] = ksrc[tid + i * 128];
            ((float4*)Vs)[tid + i * 128] = vsrc[tid + i * 128];
        }
        __syncthreads();

        float tm = -1e30f;
        #pragma unroll 2
        for (int t = 0; t < 64; t++) {
            const float* kr = Ks + t * 64;
            float s0 = 0.f, s1 = 0.f, s2 = 0.f, s3 = 0.f;
            #pragma unroll
            for (int d = 0; d < 64; d += 4) {
                s0 += q[d]   * kr[d];
                s1 += q[d+1] * kr[d+1];
                s2 += q[d+2] * kr[d+2];
                s3 += q[d+3] * kr[d+3];
            }
            float sv = ((s0 + s1) + (s2 + s3)) * 0.125f;  // 1/sqrt(64)
            myrow[t] = sv;
            tm = fmaxf(tm, sv);
        }

        const float newm = fmaxf(mx, tm);
        const float corr = __expf(mx - newm);
        l *= corr;
        #pragma unroll
        for (int d = 0; d < 64; d++) acc[d] *= corr;

        #pragma unroll 2
        for (int t = 0; t < 64; t++) {
            const float p = __expf(myrow[t] - newm);
            l += p;
            const float* vr = Vs + t * 64;
            #pragma unroll
            for (int d = 0; d < 64; d++) acc[d] += p * vr[d];
        }
        mx = newm;
    }

    const float inv = 1.f / l;
    const size_t ro = ((size_t)(bv * SEQ + srow)) * EMB + h * HD;
    __nv_bfloat162* hp = (__nv_bfloat162*)(Ohi + ro);
    __nv_bfloat162* lp = (__nv_bfloat162*)(Olo + ro);
    #pragma unroll
    for (int i = 0; i < 32; i++) {
        float v0 = acc[2*i] * inv, v1 = acc[2*i+1] * inv;
        __nv_bfloat16 h0 = __float2bfloat16(v0), h1 = __float2bfloat16(v1);
        __nv_bfloat162 hh; hh.x = h0; hh.y = h1;
        hp[i] = hh;
        __nv_bfloat162 ll;
        ll.x = __float2bfloat16(v0 - __bfloat162float(h0));
        ll.y = __float2bfloat16(v1 - __bfloat162float(h1));
        lp[i] = ll;
    }
}

// ---------------------------------------------------------------------------
extern "C" void kernel_launch(void* const* d_in, const int* in_sizes, int n_in,
                              void* d_out, int out_size)
{
    const float* x    = (const float*)d_in[0];
    const float* Wqkv = (const float*)d_in[1];
    const float* bqkv = (const float*)d_in[2];
    const float* Wo   = (const float*)d_in[3];
    const float* bo   = (const float*)d_in[4];
    float* out = (float*)d_out;

    float *qkv;
    __nv_bfloat16 *Ahi, *Alo, *B1hi, *B1lo, *B2hi, *B2lo, *A2hi, *A2lo;
    cudaGetSymbolAddress((void**)&qkv,  g_qkv);
    cudaGetSymbolAddress((void**)&Ahi,  g_Ahi);
    cudaGetSymbolAddress((void**)&Alo,  g_Alo);
    cudaGetSymbolAddress((void**)&B1hi, g_B1hi);
    cudaGetSymbolAddress((void**)&B1lo, g_B1lo);
    cudaGetSymbolAddress((void**)&B2hi, g_B2hi);
    cudaGetSymbolAddress((void**)&B2lo, g_B2lo);
    cudaGetSymbolAddress((void**)&A2hi, g_A2hi);
    cudaGetSymbolAddress((void**)&A2lo, g_A2lo);

    cudaFuncSetAttribute(gemm_mma<0>, cudaFuncAttributeMaxDynamicSharedMemorySize, MM_SMEM);
    cudaFuncSetAttribute(gemm_mma<1>, cudaFuncAttributeMaxDynamicSharedMemorySize, MM_SMEM);
    cudaFuncSetAttribute(attn_kernel, cudaFuncAttributeMaxDynamicSharedMemorySize, ATTN_SMEM);

    // 0) split x -> bf16 hi/lo; transpose+split weights -> [N,K] bf16
    cvt_hilo<<<(MROWS*EMB/4 + 255)/256, 256>>>(x, Ahi, Alo, MROWS*EMB/4);
    cvt_transpose<<<dim3(NQKV/32, EMB/32), dim3(32, 8)>>>(Wqkv, B1hi, B1lo, EMB, NQKV);
    cvt_transpose<<<dim3(EMB/32,  EMB/32), dim3(32, 8)>>>(Wo,   B2hi, B2lo, EMB, EMB);

    // 1) QKV projection (mma.sync) -> scatter into [qkv][bv][h][s][d]
    gemm_mma<1><<<dim3(NQKV/128, MROWS/128), 256, MM_SMEM>>>(
        Ahi, Alo, B1hi, B1lo, bqkv, qkv, NQKV, EMB);

    // 2) Flash attention -> split-bf16 [bv*s][h*d]
    attn_kernel<<<dim3(SEQ/128, NH, BVN), 128, ATTN_SMEM>>>(qkv, A2hi, A2lo);

    // 3) Output projection (mma.sync) -> d_out
    gemm_mma<0><<<dim3(EMB/128, MROWS/128), 256, MM_SMEM>>>(
        A2hi, A2lo, B2hi, B2lo, bo, out, EMB, EMB);
}